// round 10
// baseline (speedup 1.0000x reference)
#include <cuda_runtime.h>
#include <cstdint>

// MergedEmbeddingBag: T=26 tables, R=100000 rows, D=128, B=4096, L=20.
// W: [T, R, D] fp32.  indices: [T, B, L] int32.  out: [T, B, D] fp32.
// Odd tables -> MEAN (/L), even -> SUM.
//
// FINAL (R7 measured-best + streaming index loads): one warp per bag; lane
// owns one float4 -> each row gather is one fully coalesced 512B warp
// transaction. Two front-batched groups of 10 __ldcg loads (L2-only: random
// gathers over a 51MB table can never hit L1, which is flushed per launch
// anyway). Indices via __ldcs (touched once — evict-first, don't displace
// table rows in L2). 32-bit offsets from the per-table base, __stcs
// evict-first output stores, 5 blocks/SM (top of the measured occupancy
// plateau). Traffic is at the compulsory floor (~807MB) and bandwidth at
// ~84% of spec — the random-512B-gather DRAM ceiling.

constexpr int T = 26;
constexpr int R = 100000;
constexpr int D = 128;
constexpr int B = 4096;
constexpr int L = 20;
constexpr int BAGS = T * B;           // 106496 bags
constexpr int D4 = D / 4;             // 32 float4 per row -> 1 per lane
constexpr int HALF = L / 2;           // 10

__global__ __launch_bounds__(256, 5)
void merged_embedding_bag_kernel(const float4* __restrict__ W4,
                                 const int* __restrict__ indices,
                                 float4* __restrict__ out4)
{
    const int gwarp = (blockIdx.x * blockDim.x + threadIdx.x) >> 5;
    const int lane  = threadIdx.x & 31;
    if (gwarp >= BAGS) return;

    const int t = gwarp / B;                 // table id
    const int* __restrict__ ip = indices + (size_t)gwarp * L;

    // Per-table base; all row offsets from here fit in 32 bits (51 MB table).
    const float4* __restrict__ wt = W4 + (size_t)t * (size_t)R * D4;

    // 20 indices up front. Bag base is 16B-aligned (L=20 ints = 80B) -> load
    // as 5x int4 streaming loads (evict-first: one-shot data, keep L2 for
    // table rows). Then convert to 32-bit float4 offsets (row*32+lane <= 3.2M).
    int raw[L];
    {
        const int4* __restrict__ ip4 = (const int4*)ip;
#pragma unroll
        for (int q = 0; q < L / 4; q++) {
            const int4 r = __ldcs(ip4 + q);
            raw[q * 4 + 0] = r.x; raw[q * 4 + 1] = r.y;
            raw[q * 4 + 2] = r.z; raw[q * 4 + 3] = r.w;
        }
    }
    unsigned off[L];
#pragma unroll
    for (int l = 0; l < L; l++) {
        int v = raw[l];
        v = v < 0 ? 0 : (v >= R ? R - 1 : v);   // defensive, free vs DRAM lat
        off[l] = (unsigned)v * (unsigned)D4 + (unsigned)lane;
    }

    float ax = 0.f, ay = 0.f, az = 0.f, aw = 0.f;

    // ---- batch 1: 10 loads in flight, then accumulate ----
    {
        float4 v[HALF];
#pragma unroll
        for (int l = 0; l < HALF; l++)
            v[l] = __ldcg(wt + off[l]);          // L2-only: no L1 allocation
#pragma unroll
        for (int l = 0; l < HALF; l++) {
            ax += v[l].x; ay += v[l].y; az += v[l].z; aw += v[l].w;
        }
    }
    // ---- batch 2 ----
    {
        float4 v[HALF];
#pragma unroll
        for (int l = 0; l < HALF; l++)
            v[l] = __ldcg(wt + off[HALF + l]);
#pragma unroll
        for (int l = 0; l < HALF; l++) {
            ax += v[l].x; ay += v[l].y; az += v[l].z; aw += v[l].w;
        }
    }

    const float s = (t & 1) ? (1.0f / (float)L) : 1.0f;
    float4 o;
    o.x = ax * s; o.y = ay * s; o.z = az * s; o.w = aw * s;

    // Streaming store: evict-first, keep L2 for the table working set.
    __stcs(&out4[(size_t)gwarp * D4 + lane], o);
}

extern "C" void kernel_launch(void* const* d_in, const int* in_sizes, int n_in,
                              void* d_out, int out_size)
{
    const float4* W4 = (const float4*)d_in[0];
    const int* indices = (const int*)d_in[1];
    float4* out4 = (float4*)d_out;

    const int threads = 256;                      // 8 warps / block
    const int warps_per_block = threads / 32;
    const int blocks = (BAGS + warps_per_block - 1) / warps_per_block;  // 13312

    merged_embedding_bag_kernel<<<blocks, threads>>>(W4, indices, out4);
}

// round 11
// speedup vs baseline: 1.0316x; 1.0316x over previous
#include <cuda_runtime.h>
#include <cstdint>

// MergedEmbeddingBag: T=26 tables, R=100000 rows, D=128, B=4096, L=20.
// W: [T, R, D] fp32.  indices: [T, B, L] int32.  out: [T, B, D] fp32.
// Odd tables -> MEAN (/L), even -> SUM.
//
// FINAL (best-measured config, R7; verbatim resubmission):
//  - One warp per bag; lane owns one float4 -> each row gather is one fully
//    coalesced 512B warp transaction (4x128B lines).
//  - Two front-batched groups of 10 __ldcg loads: measured-best MLP shape.
//    L2-only caching — random gathers over a 51MB table can never hit L1
//    (which is flushed per launch anyway); skipping L1 allocation relieves
//    the L1tex wavefront queue (the one change that measurably helped).
//  - 32-bit float4 offsets from the per-table base (51MB < 4GB).
//  - __stcs evict-first output stores: keep L2 for the table working set.
//  - 5 blocks/SM: top of the measured (flat) occupancy curve.
// Measured: ~121us, DRAM ~84% of 8TB/s, traffic at the compulsory floor
// (~805MB: unique rows + output + indices; L2 serves all row repeats).
// Remaining gap to spec is DRAM-device-side random-burst overhead.

constexpr int T = 26;
constexpr int R = 100000;
constexpr int D = 128;
constexpr int B = 4096;
constexpr int L = 20;
constexpr int BAGS = T * B;           // 106496 bags
constexpr int D4 = D / 4;             // 32 float4 per row -> 1 per lane
constexpr int HALF = L / 2;           // 10

__global__ __launch_bounds__(256, 5)
void merged_embedding_bag_kernel(const float4* __restrict__ W4,
                                 const int* __restrict__ indices,
                                 float4* __restrict__ out4)
{
    const int gwarp = (blockIdx.x * blockDim.x + threadIdx.x) >> 5;
    const int lane  = threadIdx.x & 31;
    if (gwarp >= BAGS) return;

    const int t = gwarp / B;                 // table id
    const int* __restrict__ ip = indices + (size_t)gwarp * L;

    // Per-table base; all row offsets from here fit in 32 bits (51 MB table).
    const float4* __restrict__ wt = W4 + (size_t)t * (size_t)R * D4;

    // 20 indices up front (warp-broadcast; ptxas vectorizes to LDG.128 x5),
    // converted to 32-bit float4 offsets (row*32 + lane <= 3.2M).
    unsigned off[L];
#pragma unroll
    for (int l = 0; l < L; l++) {
        int v = ip[l];
        v = v < 0 ? 0 : (v >= R ? R - 1 : v);   // defensive, free vs DRAM lat
        off[l] = (unsigned)v * (unsigned)D4 + (unsigned)lane;
    }

    float ax = 0.f, ay = 0.f, az = 0.f, aw = 0.f;

    // ---- batch 1: 10 loads in flight, then accumulate ----
    {
        float4 v[HALF];
#pragma unroll
        for (int l = 0; l < HALF; l++)
            v[l] = __ldcg(wt + off[l]);          // L2-only: no L1 allocation
#pragma unroll
        for (int l = 0; l < HALF; l++) {
            ax += v[l].x; ay += v[l].y; az += v[l].z; aw += v[l].w;
        }
    }
    // ---- batch 2 ----
    {
        float4 v[HALF];
#pragma unroll
        for (int l = 0; l < HALF; l++)
            v[l] = __ldcg(wt + off[HALF + l]);
#pragma unroll
        for (int l = 0; l < HALF; l++) {
            ax += v[l].x; ay += v[l].y; az += v[l].z; aw += v[l].w;
        }
    }

    const float s = (t & 1) ? (1.0f / (float)L) : 1.0f;
    float4 o;
    o.x = ax * s; o.y = ay * s; o.z = az * s; o.w = aw * s;

    // Streaming store: evict-first, keep L2 for the table working set.
    __stcs(&out4[(size_t)gwarp * D4 + lane], o);
}

extern "C" void kernel_launch(void* const* d_in, const int* in_sizes, int n_in,
                              void* d_out, int out_size)
{
    const float4* W4 = (const float4*)d_in[0];
    const int* indices = (const int*)d_in[1];
    float4* out4 = (float4*)d_out;

    const int threads = 256;                      // 8 warps / block
    const int warps_per_block = threads / 32;
    const int blocks = (BAGS + warps_per_block - 1) / warps_per_block;  // 13312

    merged_embedding_bag_kernel<<<blocks, threads>>>(W4, indices, out4);
}